// round 11
// baseline (speedup 1.0000x reference)
#include <cuda_runtime.h>
#include <cuda_fp16.h>
#include <cstdint>

constexpr int NA = 1024, NB = 1024, DD = 512, KK = 256;
constexpr int XROWS = NA + NB;
constexpr unsigned int GRID = 128;
constexpr int NTH = 512;

// Device scratch
__device__ __half g_Xh[XROWS * DD];
__device__ __half g_Xl[NB * DD];
__device__ __half g_Fh[KK * DD];
__device__ __half g_Fl[KK * DD];
__device__ __half g_Ph[NA * KK];
__device__ __half g_Mb[NB * KK];
__device__ unsigned int g_bar_cnt;   // zero-init; monotonic across replays

// ---------------------------------------------------------------------------
// PTX helpers
// ---------------------------------------------------------------------------
__device__ __forceinline__ uint32_t smem_u32(const void* p) {
    uint32_t r;
    asm("{ .reg .u64 t; cvta.to.shared.u64 t, %1; cvt.u32.u64 %0, t; }" : "=r"(r) : "l"(p));
    return r;
}
__device__ __forceinline__ void cp16(uint32_t dst, const void* src) {
    asm volatile("cp.async.cg.shared.global [%0], [%1], 16;" :: "r"(dst), "l"(src) : "memory");
}
__device__ __forceinline__ void cp_commit() { asm volatile("cp.async.commit_group;" ::: "memory"); }
__device__ __forceinline__ void cp_wait1()  { asm volatile("cp.async.wait_group 1;" ::: "memory"); }
__device__ __forceinline__ void cp_wait0()  { asm volatile("cp.async.wait_group 0;" ::: "memory"); }

__device__ __forceinline__ void bar_group(int g) {
    asm volatile("bar.sync %0, %1;" :: "r"(g + 1), "r"(256) : "memory");
}

__device__ __forceinline__ void ldm_x4(uint32_t* r, uint32_t addr) {
    asm volatile("ldmatrix.sync.aligned.m8n8.x4.shared.b16 {%0,%1,%2,%3}, [%4];"
                 : "=r"(r[0]), "=r"(r[1]), "=r"(r[2]), "=r"(r[3]) : "r"(addr));
}
__device__ __forceinline__ void mma_f16(float* d, const uint32_t* a, const uint32_t* b) {
    asm volatile(
        "mma.sync.aligned.m16n8k16.row.col.f32.f16.f16.f32 "
        "{%0,%1,%2,%3}, {%4,%5,%6,%7}, {%8,%9}, {%0,%1,%2,%3};"
        : "+f"(d[0]), "+f"(d[1]), "+f"(d[2]), "+f"(d[3])
        : "r"(a[0]), "r"(a[1]), "r"(a[2]), "r"(a[3]), "r"(b[0]), "r"(b[1]));
}

constexpr uint32_t TSTR = 144;
constexpr uint32_t ARR  = 64 * TSTR;   // 9216

__device__ __forceinline__ uint32_t a_addr(uint32_t base, int row0, int lane, int koff) {
    return base + (uint32_t)(row0 + (lane & 15)) * TSTR + (uint32_t)koff + ((lane >> 4) << 4);
}
__device__ __forceinline__ uint32_t b_addr(uint32_t base, int row0, int lane, int koff) {
    return base + (uint32_t)(row0 + (lane & 7) + ((lane >> 4) << 3)) * TSTR
                + (uint32_t)koff + (((lane >> 3) & 1) << 4);
}

// Grid-wide barrier: 1 CTA/SM, grid <= #SM -> all co-resident. Monotonic
// counter is replay-safe (each barrier instance is a contiguous block).
__device__ __forceinline__ void grid_barrier() {
    __syncthreads();
    if (threadIdx.x == 0) {
        __threadfence();
        const unsigned int arrival = atomicAdd(&g_bar_cnt, 1u);
        const unsigned int target = (arrival / GRID + 1u) * GRID;
        unsigned int v;
        do {
            asm volatile("ld.acquire.gpu.u32 %0, [%1];" : "=r"(v) : "l"(&g_bar_cnt));
        } while (v < target);
    }
    __syncthreads();
}

// fp32 -> fp16 split packers
__device__ __forceinline__ uint32_t hpack(float x, float y) {
    __half2 t = __float22half2_rn(make_float2(x, y));
    return *reinterpret_cast<uint32_t*>(&t);
}
__device__ __forceinline__ uint4 hi4(const float4& v0, const float4& v1) {
    return make_uint4(hpack(v0.x, v0.y), hpack(v0.z, v0.w),
                      hpack(v1.x, v1.y), hpack(v1.z, v1.w));
}
__device__ __forceinline__ uint4 lo4(const float4& v0, const float4& v1) {
    float l[8];
    const float xs[8] = {v0.x, v0.y, v0.z, v0.w, v1.x, v1.y, v1.z, v1.w};
#pragma unroll
    for (int i = 0; i < 8; i++)
        l[i] = xs[i] - __half2float(__float2half(xs[i]));
    return make_uint4(hpack(l[0], l[1]), hpack(l[2], l[3]),
                      hpack(l[4], l[5]), hpack(l[6], l[7]));
}

// smem: per warp-group buffer rings
constexpr uint32_t S1_BUF  = 4 * ARR;             // Xh, Xl, Fh, Fl = 36864
constexpr uint32_t S1_GRP  = 3 * S1_BUF;          // 110592 per group
constexpr int SMEM_DYN     = 2 * S1_GRP;          // 221184 (max opt-in ~227KB)
constexpr uint32_t S2_BUF  = 3 * ARR;             // Ph(64)+Mb(128) = 27648
constexpr uint32_t S2_GRP  = 2 * S2_BUF;          // 55296 per group

// ---------------------------------------------------------------------------
__global__ __launch_bounds__(NTH, 1) void fused_kernel(
    const float* __restrict__ a, const float* __restrict__ b,
    const float* __restrict__ feats, float* __restrict__ out)
{
    extern __shared__ char dsm[];
    const uint32_t sb = smem_u32(dsm);

    const int tid = threadIdx.x;
    const int bid = blockIdx.x;
    const int g    = tid >> 8;        // warp-group 0/1
    const int ltid = tid & 255;
    const int lane = ltid & 31;
    const int lwid = ltid >> 5;       // warp id within group: 0..7

    // =======================================================================
    // Phase 0: convert. a: hi only; b: hi+lo; feats: hi+lo.  65536 threads.
    // =======================================================================
    {
        const int gt = bid * NTH + tid;          // 0..65535
        {
            const int base = gt * 8;             // covers 524288 floats exactly
            const float4 v0 = *reinterpret_cast<const float4*>(a + base);
            const float4 v1 = *reinterpret_cast<const float4*>(a + base + 4);
            *reinterpret_cast<uint4*>(g_Xh + base) = hi4(v0, v1);
        }
        {
            const int base = gt * 8;
            const float4 v0 = *reinterpret_cast<const float4*>(b + base);
            const float4 v1 = *reinterpret_cast<const float4*>(b + base + 4);
            *reinterpret_cast<uint4*>(g_Xh + NA * DD + base) = hi4(v0, v1);
            *reinterpret_cast<uint4*>(g_Xl + base)           = lo4(v0, v1);
        }
        if (bid * NTH + tid < 16384) {
            const int base = (bid * NTH + tid) * 8;
            const float4 v0 = *reinterpret_cast<const float4*>(feats + base);
            const float4 v1 = *reinterpret_cast<const float4*>(feats + base + 4);
            *reinterpret_cast<uint4*>(g_Fh + base) = hi4(v0, v1);
            *reinterpret_cast<uint4*>(g_Fl + base) = lo4(v0, v1);
        }
    }

    grid_barrier();

    // =======================================================================
    // Phase 1: C[2048x256] = X · F^T ; split-K across 2 warp-groups.
    //   group g handles chunks [4g, 4g+4) of 8. Tile 64x64, warp 16x32.
    // =======================================================================
    {
        const int wm = lwid & 3;          // 4 warp rows x 16
        const int wn = lwid >> 2;         // 2 warp cols x 32
        const int m0 = (bid >> 2) * 64;
        const int n0 = (bid & 3) * 64;
        const bool isA = (m0 < NA);

        const __half* pXh = g_Xh + (size_t)m0 * DD;
        const __half* pXl = g_Xl + (size_t)(isA ? 0 : m0 - NA) * DD;
        const __half* pFh = g_Fh + (size_t)n0 * DD;
        const __half* pFl = g_Fl + (size_t)n0 * DD;

        const uint32_t gb = sb + (uint32_t)g * S1_GRP;
        const int lr = ltid >> 3, ls = ltid & 7;

        auto load_chunk = [&](int c, uint32_t buf) {   // c = absolute chunk id
            const int d0 = c * 64;
#pragma unroll
            for (int pass = 0; pass < 2; pass++) {
                const int r = lr + pass * 32;
                const size_t off = (size_t)r * DD + d0 + ls * 8;
                const uint32_t sm = buf + (uint32_t)r * TSTR + (uint32_t)(ls << 4);
                cp16(sm + 0 * ARR, pXh + off);
                cp16(sm + 2 * ARR, pFh + off);
                if (!isA) {
                    cp16(sm + 1 * ARR, pXl + off);
                    cp16(sm + 3 * ARR, pFl + off);
                }
            }
            cp_commit();
        };

        load_chunk(g * 4 + 0, gb);
        load_chunk(g * 4 + 1, gb + S1_BUF);

        float acc[4][4] = {};

        for (int i = 0; i < 4; i++) {
            if (i + 1 < 4) cp_wait1(); else cp_wait0();
            bar_group(g);
            if (i + 2 < 4) load_chunk(g * 4 + i + 2, gb + (uint32_t)((i + 2) % 3) * S1_BUF);

            const uint32_t bb = gb + (uint32_t)(i % 3) * S1_BUF;
#pragma unroll
            for (int ks = 0; ks < 4; ks++) {
                const int koff = ks * 32;
                uint32_t ah[4], fh[2][4];
                ldm_x4(ah, a_addr(bb + 0 * ARR, wm * 16, lane, koff));
#pragma unroll
                for (int p = 0; p < 2; p++)
                    ldm_x4(fh[p], b_addr(bb + 2 * ARR, wn * 32 + p * 16, lane, koff));
                if (isA) {
#pragma unroll
                    for (int nt = 0; nt < 4; nt++)
                        mma_f16(acc[nt], ah, &fh[nt >> 1][(nt & 1) * 2]);
                } else {
                    uint32_t al[4], fl[2][4];
                    ldm_x4(al, a_addr(bb + 1 * ARR, wm * 16, lane, koff));
#pragma unroll
                    for (int p = 0; p < 2; p++)
                        ldm_x4(fl[p], b_addr(bb + 3 * ARR, wn * 32 + p * 16, lane, koff));
#pragma unroll
                    for (int nt = 0; nt < 4; nt++) {
                        const uint32_t* bh = &fh[nt >> 1][(nt & 1) * 2];
                        const uint32_t* bl = &fl[nt >> 1][(nt & 1) * 2];
                        mma_f16(acc[nt], ah, bh);
                        mma_f16(acc[nt], ah, bl);
                        mma_f16(acc[nt], al, bh);
                    }
                }
            }
        }

        // Cross-group K reduction + epilogue (group 0 finishes)
        float* red = reinterpret_cast<float*>(dsm);
        __syncthreads();
        if (g == 1) {
#pragma unroll
            for (int nt = 0; nt < 4; nt++)
#pragma unroll
                for (int j = 0; j < 4; j++)
                    red[ltid * 16 + nt * 4 + j] = acc[nt][j];
        }
        __syncthreads();
        if (g == 0) {
#pragma unroll
            for (int nt = 0; nt < 4; nt++)
#pragma unroll
                for (int j = 0; j < 4; j++)
                    acc[nt][j] += red[ltid * 16 + nt * 4 + j];
#pragma unroll
            for (int nt = 0; nt < 4; nt++)
#pragma unroll
                for (int h = 0; h < 2; h++) {
                    const int grow = m0 + wm * 16 + (lane >> 2) + h * 8;
                    const int col  = n0 + wn * 32 + nt * 8 + (lane & 3) * 2;
                    const float v0 = acc[nt][h * 2 + 0];
                    const float v1 = acc[nt][h * 2 + 1];
                    if (isA) {
                        const size_t idx = (size_t)grow * KK + col;
                        *reinterpret_cast<__half2*>(g_Ph + idx) =
                            __half2(__float2half(fmaxf(v0, 0.0f)),
                                    __float2half(fmaxf(v1, 0.0f)));
                    } else {
                        const size_t idx = (size_t)(grow - NA) * KK + col;
                        *reinterpret_cast<__half2*>(g_Mb + idx) =
                            __half2(__float2half(v0 <= 0.0f ? 1.0f : 0.0f),
                                    __float2half(v1 <= 0.0f ? 1.0f : 0.0f));
                    }
                }
        }
    }

    grid_barrier();

    // =======================================================================
    // Phase 2: out = Ph · Mb^T ; split-K across 2 warp-groups (2 chunks each).
    // Tile 64(M) x 128(N), warp 32x32.
    // =======================================================================
    {
        const int wm = lwid & 1;          // 2 warp rows x 32
        const int wn = lwid >> 1;         // 4 warp cols x 32
        const int i0 = (bid >> 3) * 64;
        const int j0 = (bid & 7) * 128;

        const __half* pPh = g_Ph + (size_t)i0 * KK;
        const __half* pMb = g_Mb + (size_t)j0 * KK;

        const uint32_t gb = sb + (uint32_t)g * S2_GRP;
        const int lr = ltid >> 3, ls = ltid & 7;

        auto load_chunk = [&](int c, uint32_t buf) {
            const int k0 = c * 64;
#pragma unroll
            for (int pass = 0; pass < 2; pass++) {
                const int r = lr + pass * 32;
                cp16(buf + (uint32_t)r * TSTR + (uint32_t)(ls << 4),
                     pPh + (size_t)r * KK + k0 + ls * 8);
            }
#pragma unroll
            for (int pass = 0; pass < 4; pass++) {
                const int r = lr + pass * 32;
                cp16(buf + ARR + (uint32_t)r * TSTR + (uint32_t)(ls << 4),
                     pMb + (size_t)r * KK + k0 + ls * 8);
            }
            cp_commit();
        };

        load_chunk(g * 2 + 0, gb);
        load_chunk(g * 2 + 1, gb + S2_BUF);

        float acc[2][4][4] = {};

        for (int i = 0; i < 2; i++) {
            if (i == 0) cp_wait1(); else cp_wait0();
            bar_group(g);
            const uint32_t bb = gb + (uint32_t)i * S2_BUF;
#pragma unroll
            for (int ks = 0; ks < 4; ks++) {
                const int koff = ks * 32;
                uint32_t ph[2][4], mb[2][4];
#pragma unroll
                for (int mt = 0; mt < 2; mt++)
                    ldm_x4(ph[mt], a_addr(bb, wm * 32 + mt * 16, lane, koff));
#pragma unroll
                for (int p = 0; p < 2; p++)
                    ldm_x4(mb[p], b_addr(bb + ARR, wn * 32 + p * 16, lane, koff));
#pragma unroll
                for (int mt = 0; mt < 2; mt++)
#pragma unroll
                    for (int nt = 0; nt < 4; nt++)
                        mma_f16(acc[mt][nt], ph[mt], &mb[nt >> 1][(nt & 1) * 2]);
            }
        }

        // Cross-group K reduction + epilogue
        float* red = reinterpret_cast<float*>(dsm);
        __syncthreads();
        if (g == 1) {
#pragma unroll
            for (int mt = 0; mt < 2; mt++)
#pragma unroll
                for (int nt = 0; nt < 4; nt++)
#pragma unroll
                    for (int j = 0; j < 4; j++)
                        red[ltid * 32 + mt * 16 + nt * 4 + j] = acc[mt][nt][j];
        }
        __syncthreads();
        if (g == 0) {
#pragma unroll
            for (int mt = 0; mt < 2; mt++)
#pragma unroll
                for (int nt = 0; nt < 4; nt++)
#pragma unroll
                    for (int j = 0; j < 4; j++)
                        acc[mt][nt][j] += red[ltid * 32 + mt * 16 + nt * 4 + j];
#pragma unroll
            for (int mt = 0; mt < 2; mt++)
#pragma unroll
                for (int nt = 0; nt < 4; nt++)
#pragma unroll
                    for (int h = 0; h < 2; h++) {
                        const int row = i0 + wm * 32 + mt * 16 + (lane >> 2) + h * 8;
                        const int col = j0 + wn * 32 + nt * 8 + (lane & 3) * 2;
                        *reinterpret_cast<float2*>(out + (size_t)row * NB + col) =
                            make_float2(acc[mt][nt][h * 2 + 0], acc[mt][nt][h * 2 + 1]);
                    }
        }
    }
}

// ---------------------------------------------------------------------------
extern "C" void kernel_launch(void* const* d_in, const int* in_sizes, int n_in,
                              void* d_out, int out_size)
{
    const float* a     = (const float*)d_in[0];
    const float* b     = (const float*)d_in[1];
    const float* feats = (const float*)d_in[2];
    float* out = (float*)d_out;
    (void)in_sizes; (void)n_in; (void)out_size;

    cudaFuncSetAttribute(fused_kernel, cudaFuncAttributeMaxDynamicSharedMemorySize, SMEM_DYN);
    fused_kernel<<<GRID, NTH, SMEM_DYN>>>(a, b, feats, out);
}

// round 12
// speedup vs baseline: 1.1100x; 1.1100x over previous
#include <cuda_runtime.h>
#include <cuda_fp16.h>
#include <cstdint>

constexpr int NA = 1024, NB = 1024, DD = 512, KK = 256;
constexpr int XROWS = NA + NB;
constexpr unsigned int GRID = 128;

// Device scratch
__device__ __half g_Xh[XROWS * DD];
__device__ __half g_Fh[KK * DD];
__device__ __half g_Ph[NA * KK];
__device__ __half g_Mb[NB * KK];
__device__ unsigned int g_bar_cnt;    // zero-init; monotonic across replays
__device__ int  g_fix_cnt;            // reset each run in phase 0
constexpr int FIXMAX = 32768;
__device__ int2 g_fix[FIXMAX];
constexpr float FIXTHR = 0.25f;

// ---------------------------------------------------------------------------
// PTX helpers
// ---------------------------------------------------------------------------
__device__ __forceinline__ uint32_t smem_u32(const void* p) {
    uint32_t r;
    asm("{ .reg .u64 t; cvta.to.shared.u64 t, %1; cvt.u32.u64 %0, t; }" : "=r"(r) : "l"(p));
    return r;
}
__device__ __forceinline__ void cp16(uint32_t dst, const void* src) {
    asm volatile("cp.async.cg.shared.global [%0], [%1], 16;" :: "r"(dst), "l"(src) : "memory");
}
__device__ __forceinline__ void cp_commit() { asm volatile("cp.async.commit_group;" ::: "memory"); }
__device__ __forceinline__ void cp_wait1()  { asm volatile("cp.async.wait_group 1;" ::: "memory"); }
__device__ __forceinline__ void cp_wait0()  { asm volatile("cp.async.wait_group 0;" ::: "memory"); }

__device__ __forceinline__ void ldm_x4(uint32_t* r, uint32_t addr) {
    asm volatile("ldmatrix.sync.aligned.m8n8.x4.shared.b16 {%0,%1,%2,%3}, [%4];"
                 : "=r"(r[0]), "=r"(r[1]), "=r"(r[2]), "=r"(r[3]) : "r"(addr));
}
__device__ __forceinline__ void mma_f16(float* d, const uint32_t* a, const uint32_t* b) {
    asm volatile(
        "mma.sync.aligned.m16n8k16.row.col.f32.f16.f16.f32 "
        "{%0,%1,%2,%3}, {%4,%5,%6,%7}, {%8,%9}, {%0,%1,%2,%3};"
        : "+f"(d[0]), "+f"(d[1]), "+f"(d[2]), "+f"(d[3])
        : "r"(a[0]), "r"(a[1]), "r"(a[2]), "r"(a[3]), "r"(b[0]), "r"(b[1]));
}

constexpr uint32_t TSTR = 144;
constexpr uint32_t ARR  = 64 * TSTR;   // 9216

__device__ __forceinline__ uint32_t a_addr(uint32_t base, int row0, int lane, int koff) {
    return base + (uint32_t)(row0 + (lane & 15)) * TSTR + (uint32_t)koff + ((lane >> 4) << 4);
}
__device__ __forceinline__ uint32_t b_addr(uint32_t base, int row0, int lane, int koff) {
    return base + (uint32_t)(row0 + (lane & 7) + ((lane >> 4) << 3)) * TSTR
                + (uint32_t)koff + (((lane >> 3) & 1) << 4);
}

// Grid-wide barrier: 1 CTA/SM, grid <= #SM -> all co-resident. Monotonic
// counter is replay-safe (each barrier instance is a contiguous block).
__device__ __forceinline__ void grid_barrier() {
    __syncthreads();
    if (threadIdx.x == 0) {
        __threadfence();
        const unsigned int arrival = atomicAdd(&g_bar_cnt, 1u);
        const unsigned int target = (arrival / GRID + 1u) * GRID;
        unsigned int v;
        do {
            asm volatile("ld.acquire.gpu.u32 %0, [%1];" : "=r"(v) : "l"(&g_bar_cnt));
        } while (v < target);
    }
    __syncthreads();
}

__device__ __forceinline__ uint32_t hpack(float x, float y) {
    __half2 t = __float22half2_rn(make_float2(x, y));
    return *reinterpret_cast<uint32_t*>(&t);
}
__device__ __forceinline__ uint4 hi4(const float4& v0, const float4& v1) {
    return make_uint4(hpack(v0.x, v0.y), hpack(v0.z, v0.w),
                      hpack(v1.x, v1.y), hpack(v1.z, v1.w));
}

// smem rings
constexpr uint32_t S1_BUF = 2 * ARR;   // Xh, Fh          = 18432
constexpr uint32_t S2_BUF = 3 * ARR;   // Ph(64)+Mb(128)  = 27648
constexpr int SMEM_DYN = 3 * S2_BUF;   // 82944 (>= 3*S1_BUF)

// ---------------------------------------------------------------------------
__global__ __launch_bounds__(256, 1) void fused_kernel(
    const float* __restrict__ a, const float* __restrict__ b,
    const float* __restrict__ feats, float* __restrict__ out)
{
    extern __shared__ char dsm[];
    const uint32_t sb = smem_u32(dsm);

    const int tid = threadIdx.x;
    const int bid = blockIdx.x;
    const int lane = tid & 31;
    const int wid = tid >> 5;
    const int gt = bid * 256 + tid;      // 0..32767

    // =======================================================================
    // Phase 0: convert hi-only.  a,b -> g_Xh ; feats -> g_Fh.  Reset fix cnt.
    // =======================================================================
    if (gt == 0) g_fix_cnt = 0;
    {
#pragma unroll
        for (int k = 0; k < 2; k++) {
            const int base = (gt + k * 32768) * 8;
            const float4 v0 = *reinterpret_cast<const float4*>(a + base);
            const float4 v1 = *reinterpret_cast<const float4*>(a + base + 4);
            *reinterpret_cast<uint4*>(g_Xh + base) = hi4(v0, v1);
        }
#pragma unroll
        for (int k = 0; k < 2; k++) {
            const int base = (gt + k * 32768) * 8;
            const float4 v0 = *reinterpret_cast<const float4*>(b + base);
            const float4 v1 = *reinterpret_cast<const float4*>(b + base + 4);
            *reinterpret_cast<uint4*>(g_Xh + NA * DD + base) = hi4(v0, v1);
        }
        if (gt < 16384) {
            const int base = gt * 8;
            const float4 v0 = *reinterpret_cast<const float4*>(feats + base);
            const float4 v1 = *reinterpret_cast<const float4*>(feats + base + 4);
            *reinterpret_cast<uint4*>(g_Fh + base) = hi4(v0, v1);
        }
    }

    grid_barrier();

    // =======================================================================
    // Phase 1: C[2048x256] = Xh · Fh^T  (single product everywhere)
    // Tile 64x64, 8 warps (warp 16x32), k-chunk 64, 3 buffers, 1 sync/chunk.
    // Epilogue: a -> Ph relu; b -> Mb mask (+ borderline append).
    // =======================================================================
    {
        const int wm = wid & 3;          // 4 warp rows x 16
        const int wn = wid >> 2;         // 2 warp cols x 32
        const int m0 = (bid >> 2) * 64;
        const int n0 = (bid & 3) * 64;
        const bool isA = (m0 < NA);

        const __half* pXh = g_Xh + (size_t)m0 * DD;
        const __half* pFh = g_Fh + (size_t)n0 * DD;

        const int lr = tid >> 3, ls = tid & 7;
        auto load_chunk = [&](int ch, uint32_t buf) {
            const int d0 = ch * 64;
#pragma unroll
            for (int pass = 0; pass < 2; pass++) {
                const int r = lr + pass * 32;
                const size_t off = (size_t)r * DD + d0 + ls * 8;
                const uint32_t sm = buf + (uint32_t)r * TSTR + (uint32_t)(ls << 4);
                cp16(sm + 0 * ARR, pXh + off);
                cp16(sm + 1 * ARR, pFh + off);
            }
            cp_commit();
        };

        constexpr int NCH = DD / 64;   // 8
        load_chunk(0, sb);
        load_chunk(1, sb + S1_BUF);

        float acc[4][4] = {};

        for (int ch = 0; ch < NCH; ch++) {
            if (ch + 1 < NCH) cp_wait1(); else cp_wait0();
            __syncthreads();
            if (ch + 2 < NCH) load_chunk(ch + 2, sb + (uint32_t)((ch + 2) % 3) * S1_BUF);

            const uint32_t bb = sb + (uint32_t)(ch % 3) * S1_BUF;
#pragma unroll
            for (int ks = 0; ks < 4; ks++) {
                const int koff = ks * 32;
                uint32_t ah[4], fh[2][4];
                ldm_x4(ah, a_addr(bb + 0 * ARR, wm * 16, lane, koff));
#pragma unroll
                for (int p = 0; p < 2; p++)
                    ldm_x4(fh[p], b_addr(bb + 1 * ARR, wn * 32 + p * 16, lane, koff));
#pragma unroll
                for (int nt = 0; nt < 4; nt++)
                    mma_f16(acc[nt], ah, &fh[nt >> 1][(nt & 1) * 2]);
            }
        }

        // Epilogue
#pragma unroll
        for (int nt = 0; nt < 4; nt++)
#pragma unroll
            for (int h = 0; h < 2; h++) {
                const int grow = m0 + wm * 16 + (lane >> 2) + h * 8;
                const int col  = n0 + wn * 32 + nt * 8 + (lane & 3) * 2;
                const float v0 = acc[nt][h * 2 + 0];
                const float v1 = acc[nt][h * 2 + 1];
                if (isA) {
                    const size_t idx = (size_t)grow * KK + col;
                    *reinterpret_cast<__half2*>(g_Ph + idx) =
                        __half2(__float2half(fmaxf(v0, 0.0f)), __float2half(fmaxf(v1, 0.0f)));
                } else {
                    const int br = grow - NA;
                    const size_t idx = (size_t)br * KK + col;
                    *reinterpret_cast<__half2*>(g_Mb + idx) =
                        __half2(__float2half(v0 <= 0.0f ? 1.0f : 0.0f),
                                __float2half(v1 <= 0.0f ? 1.0f : 0.0f));
                    if (fabsf(v0) < FIXTHR) {
                        const int p = atomicAdd(&g_fix_cnt, 1);
                        if (p < FIXMAX) g_fix[p] = make_int2(br, col);
                    }
                    if (fabsf(v1) < FIXTHR) {
                        const int p = atomicAdd(&g_fix_cnt, 1);
                        if (p < FIXMAX) g_fix[p] = make_int2(br, col + 1);
                    }
                }
            }
    }

    grid_barrier();

    // =======================================================================
    // Phase 1.5: exact fp32 fixup of borderline mask entries.
    // =======================================================================
    {
        int n = g_fix_cnt;
        if (n > FIXMAX) n = FIXMAX;
        const int gw = bid * 8 + wid;              // 1024 warps
        for (int e = gw; e < n; e += GRID * 8) {
            const int2 rc = g_fix[e];
            const float* br = b + (size_t)rc.x * DD;
            const float* fr = feats + (size_t)rc.y * DD;
            float s = 0.0f;
#pragma unroll
            for (int i = 0; i < 16; i++) {
                const int idx = i * 32 + lane;
                s = fmaf(br[idx], fr[idx], s);
            }
#pragma unroll
            for (int o = 16; o; o >>= 1)
                s += __shfl_xor_sync(0xFFFFFFFFu, s, o);
            if (lane == 0)
                g_Mb[(size_t)rc.x * KK + rc.y] = __float2half(s <= 0.0f ? 1.0f : 0.0f);
        }
    }

    grid_barrier();

    // =======================================================================
    // Phase 2: out = Ph · Mb^T.  Tile 64x128, warp 32x32, 4 chunks, 3 bufs.
    // =======================================================================
    {
        const int wm = wid & 1;          // 2 warp rows x 32
        const int wn = wid >> 1;         // 4 warp cols x 32
        const int i0 = (bid >> 3) * 64;
        const int j0 = (bid & 7) * 128;

        const __half* pPh = g_Ph + (size_t)i0 * KK;
        const __half* pMb = g_Mb + (size_t)j0 * KK;

        const int lr = tid >> 3, ls = tid & 7;
        auto load_chunk = [&](int ch, uint32_t buf) {
            const int k0 = ch * 64;
#pragma unroll
            for (int pass = 0; pass < 2; pass++) {
                const int r = lr + pass * 32;
                cp16(buf + (uint32_t)r * TSTR + (uint32_t)(ls << 4),
                     pPh + (size_t)r * KK + k0 + ls * 8);
            }
#pragma unroll
            for (int pass = 0; pass < 4; pass++) {
                const int r = lr + pass * 32;
                cp16(buf + ARR + (uint32_t)r * TSTR + (uint32_t)(ls << 4),
                     pMb + (size_t)r * KK + k0 + ls * 8);
            }
            cp_commit();
        };

        constexpr int NCH = KK / 64;   // 4
        load_chunk(0, sb);
        load_chunk(1, sb + S2_BUF);

        float acc[2][4][4] = {};

        for (int ch = 0; ch < NCH; ch++) {
            if (ch + 1 < NCH) cp_wait1(); else cp_wait0();
            __syncthreads();
            if (ch + 2 < NCH) load_chunk(ch + 2, sb + (uint32_t)((ch + 2) % 3) * S2_BUF);

            const uint32_t bb = sb + (uint32_t)(ch % 3) * S2_BUF;
#pragma unroll
            for (int ks = 0; ks < 4; ks++) {
                const int koff = ks * 32;
                uint32_t ph[2][4], mb[2][4];
#pragma unroll
                for (int mt = 0; mt < 2; mt++)
                    ldm_x4(ph[mt], a_addr(bb, wm * 32 + mt * 16, lane, koff));
#pragma unroll
                for (int p = 0; p < 2; p++)
                    ldm_x4(mb[p], b_addr(bb + ARR, wn * 32 + p * 16, lane, koff));
#pragma unroll
                for (int mt = 0; mt < 2; mt++)
#pragma unroll
                    for (int nt = 0; nt < 4; nt++)
                        mma_f16(acc[mt][nt], ph[mt], &mb[nt >> 1][(nt & 1) * 2]);
            }
        }

#pragma unroll
        for (int mt = 0; mt < 2; mt++)
#pragma unroll
            for (int nt = 0; nt < 4; nt++)
#pragma unroll
                for (int h = 0; h < 2; h++) {
                    const int row = i0 + wm * 32 + mt * 16 + (lane >> 2) + h * 8;
                    const int col = j0 + wn * 32 + nt * 8 + (lane & 3) * 2;
                    *reinterpret_cast<float2*>(out + (size_t)row * NB + col) =
                        make_float2(acc[mt][nt][h * 2 + 0], acc[mt][nt][h * 2 + 1]);
                }
    }
}

// ---------------------------------------------------------------------------
extern "C" void kernel_launch(void* const* d_in, const int* in_sizes, int n_in,
                              void* d_out, int out_size)
{
    const float* a     = (const float*)d_in[0];
    const float* b     = (const float*)d_in[1];
    const float* feats = (const float*)d_in[2];
    float* out = (float*)d_out;
    (void)in_sizes; (void)n_in; (void)out_size;

    cudaFuncSetAttribute(fused_kernel, cudaFuncAttributeMaxDynamicSharedMemorySize, SMEM_DYN);
    fused_kernel<<<GRID, 256, SMEM_DYN>>>(a, b, feats, out);
}